// round 12
// baseline (speedup 1.0000x reference)
#include <cuda_runtime.h>

#define EE 25
#define HH 37
#define NJ 6
#define PEC 27                   // padded cols (f2 per plane row)
#define PHR 40                   // padded rows + guard
#define PLANE2 (PHR * PEC)       // 1080 f2 per plane
#define NF2 (3 * PLANE2)         // 3240 f2 per buffer (3 planes)
#define SBAT2 (2 * NF2)          // f2 per batch (ping+pong)
#define NB 2                     // batches per CTA
#define SMEM_F2 (NB * SBAT2)     // 12960 f2
#define NTH 480
#define NBAND 19
#define NVP (NBAND * EE)         // 475 vertical pairs
#define GAMMA 0.9f
#define ADDC 12
#define MROW (HH * (NJ + 1))     // 259 mask rows per batch

// dr = {0,1,1,0,-1,-1} ; dc = {1,0,-1,-1,0,1}  packed (d+1), 2 bits per k
#define DR_PACK 105u
#define DC_PACK 2310u

#define SMEM_WORDS (2 * SMEM_F2 + NB * MROW)
#define SMEM_BYTES (SMEM_WORDS * 4)

__global__ __launch_bounds__(NTH, 2) void vin_kernel(
    const float* __restrict__ goals,   // [B,6,25,25]
    const int*   __restrict__ state,   // [B,3]
    const float* __restrict__ obst,    // [B,25,25]
    const int*   __restrict__ n_iter,  // [1]
    float* __restrict__ out)           // [B,4]
{
    extern __shared__ float sm[];
    float2* smf2 = (float2*)sm;
    unsigned* obsh = (unsigned*)(sm + 2 * SMEM_F2);  // [NB][37]
    unsigned* gbsh = obsh + NB * HH;                 // [NB][6*37]

    const int b0  = blockIdx.x * NB;
    const int tid = threadIdx.x;

    // zero all float buffers (incl. halos & guard rows)
    for (int i = tid; i < 2 * SMEM_F2; i += NTH) sm[i] = 0.0f;

    // build bitmasks for both batches (tt<37 -> obstacle row, else goal row)
    for (int t = tid; t < NB * MROW; t += NTH) {
        int X  = t / MROW;
        int tt = t - X * MROW;
        int bb = b0 + X;
        int r, j;
        if (tt < HH) { r = tt; j = -1; }
        else         { int t2 = tt - HH; j = t2 / HH; r = t2 - j * HH; }
        unsigned bits = 0u;
        #pragma unroll 1
        for (int c = 0; c < EE; ++c) {
            int u = r + (c >> 1) - ADDC;
            if (u >= 0 && u < EE) {
                if (j < 0) {
                    if (obst[(bb * EE + u) * EE + c] == 0.0f) bits |= (1u << c);
                } else {
                    if (goals[((bb * NJ + j) * EE + u) * EE + c] != 0.0f) bits |= (1u << c);
                }
            }
        }
        if (j < 0) obsh[X * HH + r] = bits;
        else       gbsh[X * NJ * HH + (tt - HH)] = bits;
    }
    __syncthreads();

    const bool active = (tid < NVP);
    int base2 = 0;     // f2 index of cell A within plane 0
    float AmA[NB], AmB[NB];
    unsigned cgA[NB], cgB[NB];
    float2 oA0[NB], oA1[NB], oA2[NB], oB0[NB], oB1[NB], oB2[NB];
    #pragma unroll
    for (int X = 0; X < NB; ++X) {
        AmA[X] = AmB[X] = 0.f; cgA[X] = cgB[X] = 0u;
        oA0[X] = oA1[X] = oA2[X] = make_float2(0.f, 0.f);
        oB0[X] = oB1[X] = oB2[X] = make_float2(0.f, 0.f);
    }

    if (active) {
        int band = tid / EE;
        int c    = tid - band * EE;
        int rA   = 2 * band;
        int rB   = rA + 1;
        base2 = (rA + 1) * PEC + (c + 1);
        int rBc = (rB < HH) ? rB : (HH - 1);

        #pragma unroll
        for (int X = 0; X < NB; ++X) {
            unsigned obA = (obsh[X * HH + rA] >> c) & 1u;
            unsigned obB = (rB < HH) ? ((obsh[X * HH + rB] >> c) & 1u) : 0u;
            AmA[X] = obA ? GAMMA : 0.0f;
            AmB[X] = obB ? GAMMA : 0.0f;
            unsigned gA = 0u, gB = 0u;
            #pragma unroll
            for (int j = 0; j < NJ; ++j) {
                gA |= ((gbsh[X * NJ * HH + j * HH + rA ] >> c) & 1u) << j;
                gB |= ((gbsh[X * NJ * HH + j * HH + rBc] >> c) & 1u) << j;
            }
            cgA[X] = obA ? gA : 0u;
            cgB[X] = obB ? gB : 0u;

            oA0[X] = make_float2((cgA[X] &  1u) ? 1.f : 0.f, (cgA[X] &  8u) ? 1.f : 0.f);
            oA1[X] = make_float2((cgA[X] &  2u) ? 1.f : 0.f, (cgA[X] & 16u) ? 1.f : 0.f);
            oA2[X] = make_float2((cgA[X] &  4u) ? 1.f : 0.f, (cgA[X] & 32u) ? 1.f : 0.f);
            oB0[X] = make_float2((cgB[X] &  1u) ? 1.f : 0.f, (cgB[X] &  8u) ? 1.f : 0.f);
            oB1[X] = make_float2((cgB[X] &  2u) ? 1.f : 0.f, (cgB[X] & 16u) ? 1.f : 0.f);
            oB2[X] = make_float2((cgB[X] &  4u) ? 1.f : 0.f, (cgB[X] & 32u) ? 1.f : 0.f);

            float2* D = smf2 + X * SBAT2 + base2;   // buffer 0
            D[0]               = oA0[X];
            D[PLANE2]          = oA1[X];
            D[2 * PLANE2]      = oA2[X];
            D[PEC]             = oB0[X];
            D[PLANE2 + PEC]    = oB1[X];
            D[2 * PLANE2 + PEC]= oB2[X];
        }
    }
    __syncthreads();

    const int iters = n_iter[0];
    int spO2 = 0;

    for (int s = 0; s < iters; ++s) {
        if (active) {
            #pragma unroll
            for (int X = 0; X < NB; ++X) {
                const float2* S = smf2 + X * SBAT2 + spO2 + base2;
                float2*       D = smf2 + X * SBAT2 + (spO2 ^ NF2) + base2;

                // 10 plane loads (coalesced: consecutive lanes -> consecutive f2)
                float2 a0 = S[1];                      // P0, dir0
                float2 a3 = S[-1];                     // P0, dir3
                float2 a4 = S[PLANE2 - PEC];           // P1, dir4
                float2 a2 = S[2 * PLANE2 + PEC - 1];   // P2, dir2
                float2 a5 = S[2 * PLANE2 - PEC + 1];   // P2, dir5
                float2 b0 = S[PEC + 1];                // P0, B dir0
                float2 b3 = S[PEC - 1];                // P0, B dir3
                float2 b1 = S[PLANE2 + 2 * PEC];       // P1, B dir1
                float2 b2 = S[2 * PLANE2 + 2 * PEC - 1]; // P2, B dir2
                float2 b5 = S[2 * PLANE2 + 1];         // P2, B dir5

                float mA0 = fmaxf(fmaxf(a0.x, a3.x),  fmaxf(oA1[X].x, oA2[X].y));
                float mA1 = fmaxf(fmaxf(oB1[X].x, a4.x), fmaxf(oA2[X].x, oA0[X].x));
                float mA2 = fmaxf(fmaxf(a2.x, a5.x),  fmaxf(oA0[X].y, oA1[X].x));
                float mA3 = fmaxf(fmaxf(a3.y, a0.y),  fmaxf(oA1[X].y, oA2[X].x));
                float mA4 = fmaxf(fmaxf(a4.y, oB1[X].y), fmaxf(oA2[X].y, oA0[X].y));
                float mA5 = fmaxf(fmaxf(a5.y, a2.y),  fmaxf(oA0[X].x, oA1[X].y));

                float mB0 = fmaxf(fmaxf(b0.x, b3.x),  fmaxf(oB1[X].x, oB2[X].y));
                float mB1 = fmaxf(fmaxf(b1.x, oA1[X].x), fmaxf(oB2[X].x, oB0[X].x));
                float mB2 = fmaxf(fmaxf(b2.x, b5.x),  fmaxf(oB0[X].y, oB1[X].x));
                float mB3 = fmaxf(fmaxf(b3.y, b0.y),  fmaxf(oB1[X].y, oB2[X].x));
                float mB4 = fmaxf(fmaxf(oA1[X].y, b1.y), fmaxf(oB2[X].y, oB0[X].y));
                float mB5 = fmaxf(fmaxf(b5.y, b2.y),  fmaxf(oB0[X].x, oB1[X].y));

                oA0[X].x = fmaf(AmA[X], mA0, (cgA[X] &  1u) ? 1.f : 0.f);
                oA0[X].y = fmaf(AmA[X], mA3, (cgA[X] &  8u) ? 1.f : 0.f);
                oA1[X].x = fmaf(AmA[X], mA1, (cgA[X] &  2u) ? 1.f : 0.f);
                oA1[X].y = fmaf(AmA[X], mA4, (cgA[X] & 16u) ? 1.f : 0.f);
                oA2[X].x = fmaf(AmA[X], mA2, (cgA[X] &  4u) ? 1.f : 0.f);
                oA2[X].y = fmaf(AmA[X], mA5, (cgA[X] & 32u) ? 1.f : 0.f);
                oB0[X].x = fmaf(AmB[X], mB0, (cgB[X] &  1u) ? 1.f : 0.f);
                oB0[X].y = fmaf(AmB[X], mB3, (cgB[X] &  8u) ? 1.f : 0.f);
                oB1[X].x = fmaf(AmB[X], mB1, (cgB[X] &  2u) ? 1.f : 0.f);
                oB1[X].y = fmaf(AmB[X], mB4, (cgB[X] & 16u) ? 1.f : 0.f);
                oB2[X].x = fmaf(AmB[X], mB2, (cgB[X] &  4u) ? 1.f : 0.f);
                oB2[X].y = fmaf(AmB[X], mB5, (cgB[X] & 32u) ? 1.f : 0.f);

                D[0]                = oA0[X];
                D[PLANE2]           = oA1[X];
                D[2 * PLANE2]       = oA2[X];
                D[PEC]              = oB0[X];
                D[PLANE2 + PEC]     = oB1[X];
                D[2 * PLANE2 + PEC] = oB2[X];
            }
        }
        spO2 ^= NF2;
        __syncthreads();
    }
    // smf2 + X*SBAT2 + spO2 holds final s_plus planes for batch X

    if (tid < 4 * NB) {
        int X     = tid >> 2;
        int a     = tid & 3;
        int bb    = b0 + X;
        int alpha = state[bb * 3 + 0];
        int u     = state[bb * 3 + 1];
        int v     = state[bb * 3 + 2];
        int rot   = (alpha + 1) % 6;
        int uu    = u - (v >> 1) + ADDC;

        int p, ddr = 0, ddc = 0;
        int drr = (int)((DR_PACK >> (2 * rot)) & 3u) - 1;
        int dcc = (int)((DC_PACK >> (2 * rot)) & 3u) - 1;
        if (a == 0)      { p = rot; ddr =  drr; ddc =  dcc; }
        else if (a == 1) { p = rot; ddr = -drr; ddc = -dcc; }
        else if (a == 2) { p = (rot + 1) % 6; }
        else             { p = (rot + 5) % 6; }

        float q = 0.0f;
        if ((obsh[X * HH + uu] >> v) & 1u) {
            int f2idx = X * SBAT2 + spO2 + (p % 3) * PLANE2
                      + (uu + ddr + 1) * PEC + (v + ddc + 1);
            q = sm[2 * f2idx + (p >= 3 ? 1 : 0)];
        }
        out[bb * 4 + a] = q;
    }
}

extern "C" void kernel_launch(void* const* d_in, const int* in_sizes, int n_in,
                              void* d_out, int out_size) {
    const float* goals  = (const float*)d_in[0];
    const int*   state  = (const int*)  d_in[1];
    const float* obst   = (const float*)d_in[2];
    const int*   n_iter = (const int*)  d_in[3];
    float* out = (float*)d_out;

    cudaFuncSetAttribute(vin_kernel,
                         cudaFuncAttributeMaxDynamicSharedMemorySize, SMEM_BYTES);

    int B = out_size / 4;        // 512
    vin_kernel<<<B / NB, NTH, SMEM_BYTES>>>(goals, state, obst, n_iter, out);
}